// round 4
// baseline (speedup 1.0000x reference)
#include <cuda_runtime.h>

// Problem shapes (fixed by reference setup_inputs)
#define N_ 4096
#define A_ 32768
#define F_ 160
#define C_ 10

// Tiling
#define BM 64          // rows (inputs) per CTA tile
#define BA 128         // addresses per A-tile
#define SPLITS 4       // 64*4=256 CTAs = single wave @ 2 CTA/SM
#define TILES_A (A_ / BA)            // 256
#define TILES_PER (TILES_A / SPLITS) // 64

// Scratch (no allocations allowed -> device globals)
__device__ float g_x2[N_];
__device__ float g_y2[A_];
__device__ float g_Yt[F_ * A_];   // Y transposed: Yt[k][a]
__device__ float g_Mt[C_ * A_];   // M transposed: Mt[c][a]
__device__ float g_num[N_ * C_];
__device__ float g_den[N_];

typedef unsigned long long u64;

__device__ __forceinline__ float fast_sqrt(float x) {
    float r;
    asm("sqrt.approx.f32 %0, %1;" : "=f"(r) : "f"(x));
    return r;
}

// Packed f32x2 FMA (FFMA2) — ptxas never emits this from C++; PTX-only.
__device__ __forceinline__ void ffma2(u64& d, u64 a, u64 b) {
    asm("fma.rn.f32x2 %0, %1, %2, %3;" : "=l"(d) : "l"(a), "l"(b), "l"(d));
}
__device__ __forceinline__ u64 pack2(float x, float y) {
    u64 r;
    asm("mov.b64 %0, {%1, %2};" : "=l"(r) : "f"(x), "f"(y));
    return r;
}
__device__ __forceinline__ float2 unpack2(u64 v) {
    float2 f;
    asm("mov.b64 {%0, %1}, %2;" : "=f"(f.x), "=f"(f.y) : "l"(v));
    return f;
}

__global__ void zero_kernel() {
    int i = blockIdx.x * blockDim.x + threadIdx.x;
    if (i < N_ * C_) g_num[i] = 0.0f;
    if (i < N_) g_den[i] = 0.0f;
}

// One warp per row: squared L2 norms of inputs (x2) and Address (y2)
__global__ void norms_kernel(const float* __restrict__ X, const float* __restrict__ Y) {
    int w = (blockIdx.x * blockDim.x + threadIdx.x) >> 5;
    int lane = threadIdx.x & 31;
    if (w >= N_ + A_) return;
    const float* p = (w < N_) ? (X + (size_t)w * F_) : (Y + (size_t)(w - N_) * F_);
    float s = 0.0f;
#pragma unroll
    for (int k = lane; k < F_; k += 32) {
        float v = p[k];
        s = fmaf(v, v, s);
    }
#pragma unroll
    for (int o = 16; o; o >>= 1) s += __shfl_xor_sync(0xffffffffu, s, o);
    if (lane == 0) {
        if (w < N_) g_x2[w] = s;
        else g_y2[w - N_] = s;
    }
}

// Tiled transpose Y [A,F] -> Yt [F,A]
__global__ void transposeY_kernel(const float* __restrict__ Y) {
    __shared__ float tile[32][33];
    int a0 = blockIdx.x * 32, k0 = blockIdx.y * 32;
    int tx = threadIdx.x, ty = threadIdx.y;  // 32 x 8
#pragma unroll
    for (int r = 0; r < 32; r += 8)
        tile[ty + r][tx] = Y[(size_t)(a0 + ty + r) * F_ + k0 + tx];
    __syncthreads();
#pragma unroll
    for (int r = 0; r < 32; r += 8)
        g_Yt[(size_t)(k0 + ty + r) * A_ + a0 + tx] = tile[tx][ty + r];
}

// Transpose M [A,C] -> Mt [C,A] (tiny)
__global__ void transposeM_kernel(const float* __restrict__ M) {
    int a = blockIdx.x * blockDim.x + threadIdx.x;
    if (a >= A_) return;
#pragma unroll
    for (int c = 0; c < C_; c++)
        g_Mt[(size_t)c * A_ + a] = M[(size_t)a * C_ + c];
}

// Fused mainloop: G-tile = X @ Y^T via FFMA2 (X resident in smem, Y streamed
// from global Yt), then d = sqrt(x2 + y2 - 2G), w = exp(-d/beta),
// den[n] += w, num[n][c] += w * Mt[c][a]. No max-subtraction needed:
// logits ~[-25, -10] are fp32-safe (weights 1e-11..1e-5, den >> denormal).
extern "C" __global__ void __launch_bounds__(256, 2)
main_kernel(const float* __restrict__ X) {
    extern __shared__ __align__(16) u64 Xsd[];   // [F_][BM] duplicated (x,x)
    __shared__ __align__(16) float s_acc[BM][C_ + 1];

    const int t = threadIdx.x;
    const int r0 = (t >> 4) * 4;   // 16 row groups * 4 rows
    const int a0 = (t & 15) * 8;   // 16 addr groups * 8 addrs
    const int row0 = blockIdx.x * BM;

    // Load entire X block (64 x 160) into smem, transposed + duplicated.
    // 2560 float4 loads / 256 threads = 10 each.
    for (int e = t; e < BM * (F_ / 4); e += 256) {
        int m = e / (F_ / 4), kq = (e % (F_ / 4)) * 4;
        float4 v = *(const float4*)(X + (size_t)(row0 + m) * F_ + kq);
        Xsd[(size_t)(kq + 0) * BM + m] = pack2(v.x, v.x);
        Xsd[(size_t)(kq + 1) * BM + m] = pack2(v.y, v.y);
        Xsd[(size_t)(kq + 2) * BM + m] = pack2(v.z, v.z);
        Xsd[(size_t)(kq + 3) * BM + m] = pack2(v.w, v.w);
    }
    __syncthreads();

    float x2r[4];
#pragma unroll
    for (int i = 0; i < 4; i++) x2r[i] = g_x2[row0 + r0 + i];

    float num[4][C_];
    float den[4];
#pragma unroll
    for (int i = 0; i < 4; i++) {
        den[i] = 0.0f;
#pragma unroll
        for (int c = 0; c < C_; c++) num[i][c] = 0.0f;
    }

    const float NEG_INV_BETA = -1.0f / 1.1f;

    const int at_begin = blockIdx.y * TILES_PER;
    const int at_end = at_begin + TILES_PER;

    for (int at = at_begin; at < at_end; ++at) {
        const int a1 = at * BA;
        const float* ybase = g_Yt + a1 + a0;

        u64 acc[4][4];  // [row][col-pair]; pair j covers cols (2j, 2j+1)
#pragma unroll
        for (int i = 0; i < 4; i++)
#pragma unroll
            for (int j = 0; j < 4; j++) acc[i][j] = 0ull;

#pragma unroll 8
        for (int k = 0; k < F_; k++) {
            ulonglong2 xp01 = *(const ulonglong2*)&Xsd[(size_t)k * BM + r0];
            ulonglong2 xp23 = *(const ulonglong2*)&Xsd[(size_t)k * BM + r0 + 2];
            // 4 consecutive floats reinterpret bit-exactly as 2 f32x2 pairs
            ulonglong2 ya = *(const ulonglong2*)(ybase + (size_t)k * A_);
            ulonglong2 yb = *(const ulonglong2*)(ybase + (size_t)k * A_ + 4);
            u64 xr[4] = {xp01.x, xp01.y, xp23.x, xp23.y};
            u64 yr[4] = {ya.x, ya.y, yb.x, yb.y};
#pragma unroll
            for (int i = 0; i < 4; i++)
#pragma unroll
                for (int j = 0; j < 4; j++)
                    ffma2(acc[i][j], xr[i], yr[j]);
        }

        // Epilogue: acc -> softmin weights, accumulate den/num
        float4 s0 = *(const float4*)(g_y2 + a1 + a0);
        float4 s1 = *(const float4*)(g_y2 + a1 + a0 + 4);
        float ysv[8] = {s0.x, s0.y, s0.z, s0.w, s1.x, s1.y, s1.z, s1.w};

        float wv[4][8];
#pragma unroll
        for (int i = 0; i < 4; i++) {
#pragma unroll
            for (int j = 0; j < 4; j++) {
                float2 g = unpack2(acc[i][j]);
                float d2a = fmaxf(x2r[i] + ysv[2 * j]     - 2.0f * g.x, 0.0f);
                float d2b = fmaxf(x2r[i] + ysv[2 * j + 1] - 2.0f * g.y, 0.0f);
                float wa = __expf(fast_sqrt(d2a) * NEG_INV_BETA);
                float wb = __expf(fast_sqrt(d2b) * NEG_INV_BETA);
                wv[i][2 * j] = wa; wv[i][2 * j + 1] = wb;
                den[i] += wa + wb;
            }
        }
#pragma unroll
        for (int c = 0; c < C_; c++) {
            float4 m0 = *(const float4*)(g_Mt + (size_t)c * A_ + a1 + a0);
            float4 m1 = *(const float4*)(g_Mt + (size_t)c * A_ + a1 + a0 + 4);
            float mj[8] = {m0.x, m0.y, m0.z, m0.w, m1.x, m1.y, m1.z, m1.w};
#pragma unroll
            for (int i = 0; i < 4; i++) {
                float s = 0.0f;
#pragma unroll
                for (int j = 0; j < 8; j++) s = fmaf(wv[i][j], mj[j], s);
                num[i][c] += s;
            }
        }
    }

    // CTA-level reduction across the 16 addr-groups, then global atomics
    __syncthreads();
    for (int e = t; e < BM * (C_ + 1); e += 256) ((float*)s_acc)[e] = 0.0f;
    __syncthreads();
#pragma unroll
    for (int i = 0; i < 4; i++) {
        atomicAdd(&s_acc[r0 + i][C_], den[i]);
#pragma unroll
        for (int c = 0; c < C_; c++) atomicAdd(&s_acc[r0 + i][c], num[i][c]);
    }
    __syncthreads();
    for (int e = t; e < BM * (C_ + 1); e += 256) {
        int r = e / (C_ + 1), c = e % (C_ + 1);
        float v = s_acc[r][c];
        if (c == C_) atomicAdd(&g_den[row0 + r], v);
        else atomicAdd(&g_num[(row0 + r) * C_ + c], v);
    }
}

__global__ void final_kernel(float* __restrict__ out) {
    int i = blockIdx.x * blockDim.x + threadIdx.x;
    if (i < N_ * C_) out[i] = g_num[i] / g_den[i / C_];
}

extern "C" void kernel_launch(void* const* d_in, const int* in_sizes, int n_in,
                              void* d_out, int out_size) {
    const float* X = (const float*)d_in[0];   // inputs  [4096, 160]
    const float* Y = (const float*)d_in[1];   // Address [32768, 160]
    const float* M = (const float*)d_in[2];   // M       [32768, 10]
    float* out = (float*)d_out;               // [4096, 10] float32

    const int smem_bytes = F_ * BM * sizeof(u64);  // 80 KB dynamic
    cudaFuncSetAttribute(main_kernel,
                         cudaFuncAttributeMaxDynamicSharedMemorySize, smem_bytes);

    zero_kernel<<<(N_ * C_ + 255) / 256, 256>>>();

    int warps = N_ + A_;
    norms_kernel<<<(warps * 32 + 255) / 256, 256>>>(X, Y);

    dim3 tgrid(A_ / 32, F_ / 32);
    transposeY_kernel<<<tgrid, dim3(32, 8)>>>(Y);
    transposeM_kernel<<<(A_ + 255) / 256, 256>>>(M);

    dim3 grid(N_ / BM, SPLITS);
    main_kernel<<<grid, 256, smem_bytes>>>(X);

    final_kernel<<<(N_ * C_ + 255) / 256, 256>>>(out);
}

// round 7
// speedup vs baseline: 3.5318x; 3.5318x over previous
#include <cuda_runtime.h>
#include <cuda_bf16.h>
#include <cstdint>

// Problem shapes (fixed by reference setup_inputs)
#define N_ 4096
#define A_ 32768
#define F_ 160
#define PITCH 168          // K padded: 336B rows -> conflict-free ldmatrix
#define C_ 10

#define BM 128             // CTA tile rows
#define BA 128             // CTA tile addresses
#define SPLITS 4           // grid = 32 x 4 = 128 CTAs
#define TILES_PER ((A_ / BA) / SPLITS)   // 64

// ---- device scratch (no allocations allowed) ----
__device__ float g_x2[N_];
__device__ float g_y2[A_];
__device__ __nv_bfloat16 g_Xh[(size_t)N_ * PITCH];
__device__ __nv_bfloat16 g_Xl[(size_t)N_ * PITCH];
__device__ __nv_bfloat16 g_Yh[(size_t)A_ * PITCH];
__device__ __nv_bfloat16 g_Yl[(size_t)A_ * PITCH];
__device__ __nv_bfloat16 g_Mp[(size_t)A_ * 16];   // M cols 0-9, ones col 10, pad
__device__ float g_num[N_ * C_];
__device__ float g_den[N_];

// ---- smem layout (bytes) ----
#define SM_XH 0
#define SM_XL (SM_XH + BM * PITCH * 2)     //  43008
#define SM_YH (SM_XL + BM * PITCH * 2)     //  86016
#define SM_YL (SM_YH + BA * PITCH * 2)     // 129024
#define SM_MP (SM_YL + BA * PITCH * 2)     // 172032 : bf16 [128][16]
#define SM_Y2 (SM_MP + BA * 16 * 2)        // 176128 : float[128]
#define SM_TOTAL (SM_Y2 + BA * 4)          // 176640

// ---- PTX helpers (baseline ISA only — no tcgen05: harness targets compute_103) ----
__device__ __forceinline__ uint32_t smem_u32(const void* p) {
    uint32_t a;
    asm("{ .reg .u64 t; cvta.to.shared.u64 t, %1; cvt.u32.u64 %0, t; }" : "=r"(a) : "l"(p));
    return a;
}
__device__ __forceinline__ void ldsm4(uint32_t (&r)[4], uint32_t addr) {
    asm volatile("ldmatrix.sync.aligned.m8n8.x4.shared.b16 {%0,%1,%2,%3}, [%4];"
                 : "=r"(r[0]), "=r"(r[1]), "=r"(r[2]), "=r"(r[3]) : "r"(addr));
}
__device__ __forceinline__ void ldsm4t(uint32_t (&r)[4], uint32_t addr) {
    asm volatile("ldmatrix.sync.aligned.m8n8.x4.trans.shared.b16 {%0,%1,%2,%3}, [%4];"
                 : "=r"(r[0]), "=r"(r[1]), "=r"(r[2]), "=r"(r[3]) : "r"(addr));
}
__device__ __forceinline__ void mma16816(float (&d)[4], const uint32_t (&a)[4],
                                         uint32_t b0, uint32_t b1) {
    asm volatile(
        "mma.sync.aligned.m16n8k16.row.col.f32.bf16.bf16.f32 "
        "{%0,%1,%2,%3}, {%4,%5,%6,%7}, {%8,%9}, {%0,%1,%2,%3};"
        : "+f"(d[0]), "+f"(d[1]), "+f"(d[2]), "+f"(d[3])
        : "r"(a[0]), "r"(a[1]), "r"(a[2]), "r"(a[3]), "r"(b0), "r"(b1));
}
__device__ __forceinline__ uint32_t pack_bf16x2(float hi, float lo) {
    uint32_t r;
    asm("cvt.rn.bf16x2.f32 %0, %1, %2;" : "=r"(r) : "f"(hi), "f"(lo));
    return r;
}
__device__ __forceinline__ float fast_sqrt(float x) {
    float r;
    asm("sqrt.approx.f32 %0, %1;" : "=f"(r) : "f"(x));
    return r;
}
__device__ __forceinline__ float fast_ex2(float x) {
    float r;
    asm("ex2.approx.f32 %0, %1;" : "=f"(r) : "f"(x));
    return r;
}

// ---- prep kernels ----
__global__ void zero_kernel() {
    int i = blockIdx.x * blockDim.x + threadIdx.x;
    if (i < N_ * C_) g_num[i] = 0.0f;
    if (i < N_) g_den[i] = 0.0f;
}

__global__ void norms_kernel(const float* __restrict__ X, const float* __restrict__ Y) {
    int w = (blockIdx.x * blockDim.x + threadIdx.x) >> 5;
    int lane = threadIdx.x & 31;
    if (w >= N_ + A_) return;
    const float* p = (w < N_) ? (X + (size_t)w * F_) : (Y + (size_t)(w - N_) * F_);
    float s = 0.0f;
#pragma unroll
    for (int k = lane; k < F_; k += 32) {
        float v = p[k];
        s = fmaf(v, v, s);
    }
#pragma unroll
    for (int o = 16; o; o >>= 1) s += __shfl_xor_sync(0xffffffffu, s, o);
    if (lane == 0) {
        if (w < N_) g_x2[w] = s;
        else g_y2[w - N_] = s;
    }
}

// Split fp32 -> bf16 hi + bf16 residual, pitch-168 rows padded with zeros.
__global__ void split_kernel(const float* __restrict__ X, const float* __restrict__ Y) {
    int idx = blockIdx.x * blockDim.x + threadIdx.x;
    int total = (N_ + A_) * (PITCH / 8);
    if (idx >= total) return;
    int r = idx / (PITCH / 8), kc = (idx % (PITCH / 8)) * 8;
    const float* src;
    __nv_bfloat16 *dh, *dl;
    if (r < N_) {
        src = X + (size_t)r * F_;
        dh = g_Xh + (size_t)r * PITCH; dl = g_Xl + (size_t)r * PITCH;
    } else {
        int a = r - N_;
        src = Y + (size_t)a * F_;
        dh = g_Yh + (size_t)a * PITCH; dl = g_Yl + (size_t)a * PITCH;
    }
    uint4 uh, ul;
    __nv_bfloat16* ph = (__nv_bfloat16*)&uh;
    __nv_bfloat16* pl = (__nv_bfloat16*)&ul;
#pragma unroll
    for (int i = 0; i < 8; i++) {
        int k = kc + i;
        float v = (k < F_) ? src[k] : 0.0f;
        __nv_bfloat16 h = __float2bfloat16(v);
        ph[i] = h;
        pl[i] = __float2bfloat16(v - __bfloat162float(h));
    }
    *(uint4*)(dh + kc) = uh;
    *(uint4*)(dl + kc) = ul;
}

// M' = bf16(M) with an appended ones column (c==10) -> den via MMA.
__global__ void mprep_kernel(const float* __restrict__ M) {
    int a = blockIdx.x * blockDim.x + threadIdx.x;
    if (a >= A_) return;
    __nv_bfloat16 row[16];
#pragma unroll
    for (int c = 0; c < 16; c++) {
        float v = (c < C_) ? M[(size_t)a * C_ + c] : (c == C_ ? 1.0f : 0.0f);
        row[c] = __float2bfloat16(v);
    }
    *(uint4*)(g_Mp + (size_t)a * 16) = *(uint4*)row;
    *(uint4*)(g_Mp + (size_t)a * 16 + 8) = *(uint4*)(row + 8);
}

// ---- main fused kernel: HMMA split-bf16 distance GEMM + softmin + HMMA W@M' ----
// Warp grid 2(m) x 4(n): each warp owns 64 rows x 32 addrs per tile.
extern "C" __global__ void __launch_bounds__(256, 1)
main_kernel() {
    extern __shared__ __align__(16) char smem[];
    const uint32_t sb = smem_u32(smem);
    const int tid = threadIdx.x, wid = tid >> 5, lane = tid & 31;
    const int warp_m = wid & 1, warp_n = wid >> 1;
    const int row0 = blockIdx.x * BM;

    // Resident X tiles (hi + lo)
    for (int e = tid; e < BM * (PITCH / 8); e += 256) {
        int r = e / (PITCH / 8), c = e % (PITCH / 8);
        *(uint4*)(smem + SM_XH + r * 336 + c * 16) =
            *(const uint4*)(g_Xh + (size_t)(row0 + r) * PITCH + c * 8);
        *(uint4*)(smem + SM_XL + r * 336 + c * 16) =
            *(const uint4*)(g_Xl + (size_t)(row0 + r) * PITCH + c * 8);
    }

    float x2r[4][2];
#pragma unroll
    for (int m = 0; m < 4; m++) {
        int rr = row0 + warp_m * 64 + m * 16 + (lane >> 2);
        x2r[m][0] = g_x2[rr];
        x2r[m][1] = g_x2[rr + 8];
    }

    float numacc[4][2][4];
#pragma unroll
    for (int m = 0; m < 4; m++)
#pragma unroll
        for (int np = 0; np < 2; np++)
#pragma unroll
            for (int q = 0; q < 4; q++) numacc[m][np][q] = 0.0f;

    // -log2(e)/1.1 : w = 2^(d * NEG_K)
    const float NEG_K = -1.31154084f;

    const uint32_t aXh = sb + SM_XH + (warp_m * 64 + (lane & 15)) * 336 + (lane >> 4) * 16;
    const uint32_t aXl = aXh + (SM_XL - SM_XH);
    const uint32_t aYh = sb + SM_YH + (warp_n * 32 + (lane & 15)) * 336 + (lane >> 4) * 16;
    const uint32_t aYl = aYh + (SM_YL - SM_YH);
    const uint32_t aMp = sb + SM_MP + (warp_n * 32 + (lane & 15)) * 32 + (lane >> 4) * 16;

    for (int at = blockIdx.y * TILES_PER, end = at + TILES_PER; at < end; ++at) {
        const int a1 = at * BA;

        __syncthreads();   // previous tile's compute done reading Y/M'/y2
        for (int e = tid; e < BA * (PITCH / 8); e += 256) {
            int r = e / (PITCH / 8), c = e % (PITCH / 8);
            *(uint4*)(smem + SM_YH + r * 336 + c * 16) =
                *(const uint4*)(g_Yh + (size_t)(a1 + r) * PITCH + c * 8);
            *(uint4*)(smem + SM_YL + r * 336 + c * 16) =
                *(const uint4*)(g_Yl + (size_t)(a1 + r) * PITCH + c * 8);
        }
        for (int e = tid; e < BA * 2; e += 256) {
            int r = e >> 1, q = e & 1;
            *(uint4*)(smem + SM_MP + r * 32 + q * 16) =
                *(const uint4*)(g_Mp + (size_t)(a1 + r) * 16 + q * 8);
        }
        if (tid < BA) ((float*)(smem + SM_Y2))[tid] = g_y2[a1 + tid];
        __syncthreads();

        // --- distance GEMM: acc = Xh.Yh^T + Xh.Yl^T + Xl.Yh^T ---
        float acc[4][4][4];
#pragma unroll
        for (int m = 0; m < 4; m++)
#pragma unroll
            for (int nf = 0; nf < 4; nf++)
#pragma unroll
                for (int q = 0; q < 4; q++) acc[m][nf][q] = 0.0f;

#pragma unroll
        for (int ks = 0; ks < 10; ks++) {
            uint32_t Ah[4][4], Al[4][4], Bh[2][4], Bl[2][4];
#pragma unroll
            for (int m = 0; m < 4; m++) {
                ldsm4(Ah[m], aXh + m * 16 * 336 + ks * 32);
                ldsm4(Al[m], aXl + m * 16 * 336 + ks * 32);
            }
#pragma unroll
            for (int p = 0; p < 2; p++) {
                ldsm4(Bh[p], aYh + p * 16 * 336 + ks * 32);
                ldsm4(Bl[p], aYl + p * 16 * 336 + ks * 32);
            }
#pragma unroll
            for (int m = 0; m < 4; m++)
#pragma unroll
                for (int p = 0; p < 2; p++)
#pragma unroll
                    for (int s = 0; s < 2; s++) {
                        const int nf = p * 2 + s;
                        mma16816(acc[m][nf], Ah[m], Bh[p][s], Bh[p][s + 2]);
                        mma16816(acc[m][nf], Ah[m], Bl[p][s], Bl[p][s + 2]);
                        mma16816(acc[m][nf], Al[m], Bh[p][s], Bh[p][s + 2]);
                    }
        }

        // --- epilogue: w = 2^(-sqrt(d2)*log2e/beta), then numacc += W @ M' ---
        uint32_t BMk[2][4];
        ldsm4t(BMk[0], aMp);
        ldsm4t(BMk[1], aMp + 16 * 32);
        const float* y2s = (const float*)(smem + SM_Y2);

#pragma unroll
        for (int m = 0; m < 4; m++) {
            uint32_t Aw[2][4];
#pragma unroll
            for (int nf = 0; nf < 4; nf++) {
                const int col = warp_n * 32 + nf * 8 + 2 * (lane & 3);
                const float ya = y2s[col], yb = y2s[col + 1];
                const float* cc = acc[m][nf];
                float d2a = fmaxf(x2r[m][0] + ya - 2.0f * cc[0], 0.0f);
                float d2b = fmaxf(x2r[m][0] + yb - 2.0f * cc[1], 0.0f);
                float d2c = fmaxf(x2r[m][1] + ya - 2.0f * cc[2], 0.0f);
                float d2d = fmaxf(x2r[m][1] + yb - 2.0f * cc[3], 0.0f);
                float w0 = fast_ex2(fast_sqrt(d2a) * NEG_K);
                float w1 = fast_ex2(fast_sqrt(d2b) * NEG_K);
                float w2 = fast_ex2(fast_sqrt(d2c) * NEG_K);
                float w3 = fast_ex2(fast_sqrt(d2d) * NEG_K);
                const int kst = nf >> 1, i0 = (nf & 1) * 2;
                Aw[kst][i0] = pack_bf16x2(w1, w0);       // row-lo, k pair
                Aw[kst][i0 + 1] = pack_bf16x2(w3, w2);   // row-hi
            }
#pragma unroll
            for (int kst = 0; kst < 2; kst++)
#pragma unroll
                for (int np = 0; np < 2; np++)
                    mma16816(numacc[m][np], Aw[kst], BMk[kst][np * 2], BMk[kst][np * 2 + 1]);
        }
    }

    // --- final extraction: numacc frags -> global atomics ---
#pragma unroll
    for (int m = 0; m < 4; m++)
#pragma unroll
        for (int np = 0; np < 2; np++)
#pragma unroll
            for (int q = 0; q < 4; q++) {
                int row = row0 + warp_m * 64 + m * 16 + (lane >> 2) + ((q >= 2) ? 8 : 0);
                int col = np * 8 + 2 * (lane & 3) + (q & 1);
                float v = numacc[m][np][q];
                if (col < C_) atomicAdd(&g_num[row * C_ + col], v);
                else if (col == C_) atomicAdd(&g_den[row], v);
            }
}

__global__ void final_kernel(float* __restrict__ out) {
    int i = blockIdx.x * blockDim.x + threadIdx.x;
    if (i < N_ * C_) out[i] = g_num[i] / g_den[i / C_];
}

extern "C" void kernel_launch(void* const* d_in, const int* in_sizes, int n_in,
                              void* d_out, int out_size) {
    const float* X = (const float*)d_in[0];   // inputs  [4096, 160]
    const float* Y = (const float*)d_in[1];   // Address [32768, 160]
    const float* M = (const float*)d_in[2];   // M       [32768, 10]
    float* out = (float*)d_out;               // [4096, 10] float32

    cudaFuncSetAttribute(main_kernel,
                         cudaFuncAttributeMaxDynamicSharedMemorySize, SM_TOTAL);

    zero_kernel<<<(N_ * C_ + 255) / 256, 256>>>();
    norms_kernel<<<((N_ + A_) * 32 + 255) / 256, 256>>>(X, Y);
    split_kernel<<<((N_ + A_) * (PITCH / 8) + 255) / 256, 256>>>(X, Y);
    mprep_kernel<<<(A_ + 255) / 256, 256>>>(M);

    dim3 grid(N_ / BM, SPLITS);
    main_kernel<<<grid, 256, SM_TOTAL>>>();

    final_kernel<<<(N_ * C_ + 255) / 256, 256>>>(out);
}